// round 15
// baseline (speedup 1.0000x reference)
#include <cuda_runtime.h>
#include <cuda_fp16.h>
#include <math.h>
#include <stdint.h>

#define T_TOK  4096
#define DMODEL 512
#define DFF    2048
#define NEXP   16
#define TOPK   2
#define NSLOTS (T_TOK*TOPK)

#define BM 128
#define BN 128
#define KC 64            // K elems per stage (64 fp16 = 128B rows)
#define MAXMT (NSLOTS/BM + NEXP)   // 80

// smem: 3 stages x (A 16KB + B 16KB) = 96KB
#define OFF_A       0
#define OFF_B       16384
#define STAGE_BYTES 32768
#define NSTAGE      3
#define SMEM_BYTES  (NSTAGE*STAGE_BYTES)

// ---------------- scratch ----------------
__device__ __half d_xf[(size_t)T_TOK * DMODEL];
__device__ __half d_w1f[(size_t)NEXP * DFF * DMODEL];
__device__ __half d_w2f[(size_t)NEXP * DMODEL * DFF];
__device__ __half d_Hf[(size_t)NSLOTS * DFF];
__device__ int   d_tok[NSLOTS];
__device__ float d_gate[NSLOTS];
__device__ int   d_counts[NEXP];
__device__ int   d_off[NEXP];
__device__ int   d_topk_idx[NSLOTS];
__device__ float d_topk_gate[NSLOTS];
__device__ uint32_t d_mtile[MAXMT];   // (e<<16)|m0
__device__ int   d_nmt;

// ---------------- PTX helpers ----------------
__device__ __forceinline__ uint32_t smem_u32(const void* p) {
    uint32_t a;
    asm("{ .reg .u64 t; cvta.to.shared.u64 t, %1; cvt.u32.u64 %0, t; }" : "=r"(a) : "l"(p));
    return a;
}
__device__ __forceinline__ void cpa16(uint32_t dst, const void* src, uint32_t srcsz) {
    asm volatile("cp.async.cg.shared.global [%0], [%1], 16, %2;"
                 :: "r"(dst), "l"(src), "r"(srcsz) : "memory");
}
#define CP_COMMIT() asm volatile("cp.async.commit_group;" ::: "memory")
#define CP_WAIT1()  asm volatile("cp.async.wait_group 1;" ::: "memory")
#define CP_WAIT0()  asm volatile("cp.async.wait_group 0;" ::: "memory")

__device__ __forceinline__ void mma16816(float* d, const uint32_t* a, const uint32_t* b) {
    asm volatile("mma.sync.aligned.m16n8k16.row.col.f32.f16.f16.f32 "
        "{%0,%1,%2,%3}, {%4,%5,%6,%7}, {%8,%9}, {%0,%1,%2,%3};"
        : "+f"(d[0]), "+f"(d[1]), "+f"(d[2]), "+f"(d[3])
        : "r"(a[0]), "r"(a[1]), "r"(a[2]), "r"(a[3]), "r"(b[0]), "r"(b[1]));
}
__device__ __forceinline__ void ldsm4(uint32_t* r, uint32_t addr) {
    asm volatile("ldmatrix.sync.aligned.m8n8.x4.shared.b16 {%0,%1,%2,%3}, [%4];"
        : "=r"(r[0]), "=r"(r[1]), "=r"(r[2]), "=r"(r[3]) : "r"(addr));
}
__device__ __forceinline__ uint32_t pack_h2(float a, float b) {
    uint32_t r;
    asm("{ .reg .f16 lo, hi; cvt.rn.f16.f32 lo, %1; cvt.rn.f16.f32 hi, %2; mov.b32 %0, {lo, hi}; }"
        : "=r"(r) : "f"(a), "f"(b));
    return r;
}

// SW128 swizzle for 128B-pitch rows
__device__ __forceinline__ uint32_t swz(int row, int cb) {
    return (uint32_t)(row * 128 + (cb ^ ((row & 7) << 4)));
}

// ---------------- router (+ fused x conversion + global histogram) ----------------
__global__ void router_kernel(const float* __restrict__ x,
                              const float* __restrict__ rw,
                              const float* __restrict__ rb)
{
    int warp = (blockIdx.x * blockDim.x + threadIdx.x) >> 5;
    int lane = threadIdx.x & 31;
    if (warp >= T_TOK) return;

    const float* xr = x + (size_t)warp * DMODEL;
    float xv[16];
#pragma unroll
    for (int i = 0; i < 16; i++) xv[i] = xr[lane + 32 * i];

#pragma unroll
    for (int i = 0; i < 16; i++)
        d_xf[(size_t)warp * DMODEL + lane + 32 * i] = __float2half_rn(xv[i]);

    float lg[NEXP];
#pragma unroll
    for (int e = 0; e < NEXP; e++) {
        const float* wr = rw + e * DMODEL;
        float p = 0.f;
#pragma unroll
        for (int i = 0; i < 16; i++) p = fmaf(xv[i], wr[lane + 32 * i], p);
#pragma unroll
        for (int o = 16; o; o >>= 1) p += __shfl_xor_sync(0xffffffffu, p, o);
        lg[e] = p + rb[e];
    }

    if (lane == 0) {
        float mx = lg[0];
#pragma unroll
        for (int e = 1; e < NEXP; e++) mx = fmaxf(mx, lg[e]);
        float pe[NEXP]; float s = 0.f;
#pragma unroll
        for (int e = 0; e < NEXP; e++) { pe[e] = expf(lg[e] - mx); s += pe[e]; }

        int i1 = 0; float v1 = pe[0];
#pragma unroll
        for (int e = 1; e < NEXP; e++) if (pe[e] > v1) { v1 = pe[e]; i1 = e; }
        int i2 = (i1 == 0) ? 1 : 0; float v2 = pe[i2];
#pragma unroll
        for (int e = 0; e < NEXP; e++)
            if (e != i1 && e != ((i1 == 0) ? 1 : 0) && pe[e] > v2) { v2 = pe[e]; i2 = e; }

        float inv = 1.f / s;
        d_topk_idx[2 * warp]      = i1;
        d_topk_gate[2 * warp]     = v1 * inv;
        d_topk_idx[2 * warp + 1]  = i2;
        d_topk_gate[2 * warp + 1] = v2 * inv;
        atomicAdd(&d_counts[i1], 1);
        atomicAdd(&d_counts[i2], 1);
    }
}

// prefix + worklist + warp-aggregated scatter, one block
__global__ void prefix_scatter_kernel() {
    __shared__ int scur[NEXP];
    if (threadIdx.x == 0) {
        int s = 0, nm = 0;
#pragma unroll
        for (int e = 0; e < NEXP; e++) {
            const int c = d_counts[e];
            d_off[e] = s; scur[e] = s;
            for (int m0 = 0; m0 < c; m0 += BM)
                d_mtile[nm++] = ((uint32_t)e << 16) | (uint32_t)m0;
            s += c;
        }
        d_nmt = nm;
    }
    __syncthreads();
    const int lane = threadIdx.x & 31;
    for (int i = threadIdx.x; i < NSLOTS; i += blockDim.x) {
        const int e = d_topk_idx[i];
        // warp-aggregated atomic: one ATOMS per distinct expert per warp
        unsigned grp = __match_any_sync(0xffffffffu, e);
        int leader = __ffs(grp) - 1;
        int rank = __popc(grp & ((1u << lane) - 1u));
        int slot;
        if (lane == leader) slot = atomicAdd(&scur[e], __popc(grp));
        slot = __shfl_sync(0xffffffffu, slot, leader) + rank;
        d_tok[slot]  = i >> 1;
        d_gate[slot] = d_topk_gate[i];
    }
}

// w1 fp32 -> fp16 (+ zero expert counters for NEXT call's router)
__global__ void wcvt1_kernel(const float* __restrict__ w1) {
    const int n4 = NEXP * DFF * DMODEL / 4;
    uint32_t* o = (uint32_t*)d_w1f;
    for (int i = blockIdx.x * blockDim.x + threadIdx.x; i < n4; i += gridDim.x * blockDim.x) {
        const float4 v = ((const float4*)w1)[i];
        o[2 * i]     = pack_h2(v.x, v.y);
        o[2 * i + 1] = pack_h2(v.z, v.w);
    }
}
// w2 fp32 -> fp16 + zero output buffer
__global__ void wcvt2_kernel(const float* __restrict__ w2, float* __restrict__ out) {
    const int z4 = T_TOK * DMODEL / 4;
    const int n4 = NEXP * DMODEL * DFF / 4;
    uint32_t* o = (uint32_t*)d_w2f;
    for (int i = blockIdx.x * blockDim.x + threadIdx.x; i < n4 + z4; i += gridDim.x * blockDim.x) {
        if (i < z4) {
            ((float4*)out)[i] = make_float4(0.f, 0.f, 0.f, 0.f);
        } else {
            const int j = i - z4;
            const float4 v = ((const float4*)w2)[j];
            o[2 * j]     = pack_h2(v.x, v.y);
            o[2 * j + 1] = pack_h2(v.z, v.w);
        }
    }
}

// zero expert counters (tiny, first on s3)
__global__ void zero_counts_kernel() {
    if (threadIdx.x < NEXP) d_counts[threadIdx.x] = 0;
}

// ---------------- fp16 HMMA grouped GEMM ----------------
// PHASE1: H = gelu(gather(xf) @ w1^T + b1) -> d_Hf
// PHASE2: out[tok] += gate * (Hf @ w2^T + b2)   (atomic accumulate)
template<int KTOT, bool PHASE1>
__global__ __launch_bounds__(256, 2)
void gemm_mma(const float* __restrict__ bias, float* __restrict__ out)
{
    constexpr int NT = PHASE1 ? DFF : DMODEL;
    constexpr int NK = KTOT / KC;
    if ((int)blockIdx.y >= d_nmt) return;
    const uint32_t mt = d_mtile[blockIdx.y];
    const int e   = (int)(mt >> 16);
    const int m0  = (int)(mt & 0xffffu);
    const int cnt = d_counts[e];
    const int n0   = blockIdx.x * BN;
    const int base = d_off[e];

    extern __shared__ __align__(128) char smem[];
    const uint32_t su = smem_u32(smem);

    const int tid = threadIdx.x;
    const int wid = tid >> 5;
    const int lid = tid & 31;

    // ---- staging roles ----
    const int r    = tid >> 1;
    const int half = tid & 1;
    const int gm   = m0 + r;
    const __half* arow = d_xf;
    uint32_t aszA = 0;
    if (gm < cnt) {
        int row = PHASE1 ? d_tok[base + gm] : (base + gm);
        arow = (PHASE1 ? d_xf : d_Hf) + (size_t)row * KTOT;
        aszA = 16;
    }
    const __half* brow = (PHASE1 ? d_w1f : d_w2f) + ((size_t)e * NT + n0 + r) * KTOT;

    uint32_t dstc[4];
#pragma unroll
    for (int j = 0; j < 4; j++) dstc[j] = swz(r, half * 64 + j * 16);

    // ---- compute layout ----
    const int wm  = (wid & 1) * 64;
    const int wn  = (wid >> 1) * 32;
    const int lr  = lid >> 2;

    const int mi    = lid >> 3;
    const int rowAl = wm + (mi & 1) * 8 + (lid & 7);
    const int cbA   = (mi >> 1) * 16;
    const int rowBl = wn + (mi >> 1) * 8 + (lid & 7);
    const int cbB   = (mi & 1) * 16;

    float acc[4][4][4];
#pragma unroll
    for (int i = 0; i < 4; i++)
#pragma unroll
        for (int j = 0; j < 4; j++)
#pragma unroll
            for (int q = 0; q < 4; q++) acc[i][j][q] = 0.f;

    auto issue = [&](int it, int buf) {
        const uint32_t sa = su + (uint32_t)buf * STAGE_BYTES + OFF_A;
        const uint32_t sb = su + (uint32_t)buf * STAGE_BYTES + OFF_B;
        const __half* pa = arow + it * KC + half * 32;
        const __half* pb = brow + it * KC + half * 32;
#pragma unroll
        for (int j = 0; j < 4; j++) {
            cpa16(sa + dstc[j], pa + j * 8, aszA);
            cpa16(sb + dstc[j], pb + j * 8, 16);
        }
    };

    uint32_t Afr[2][16], Bfr[2][8];

    auto ldfrag = [&](uint32_t sa, uint32_t sbb, int kb2, uint32_t* A, uint32_t* B) {
#pragma unroll
        for (int mf = 0; mf < 4; ++mf)
            ldsm4(A + mf * 4, sa + swz(rowAl + mf * 16, kb2 + cbA));
#pragma unroll
        for (int p = 0; p < 2; ++p)
            ldsm4(B + p * 4, sbb + swz(rowBl + p * 16, kb2 + cbB));
    };

    issue(0, 0); CP_COMMIT();
    issue(1, 1); CP_COMMIT();
    CP_WAIT1();
    __syncthreads();
    ldfrag(su + OFF_A, su + OFF_B, 0, Afr[0], Bfr[0]);

    for (int it = 0; it < NK; ++it) {
        const int buf = it % NSTAGE;
        const uint32_t sa  = su + (uint32_t)buf * STAGE_BYTES + OFF_A;
        const uint32_t sbb = su + (uint32_t)buf * STAGE_BYTES + OFF_B;
#pragma unroll
        for (int kk = 0; kk < 4; ++kk) {
            const int cur = kk & 1;
            if (kk < 3) {
                ldfrag(sa, sbb, (kk + 1) * 32, Afr[cur ^ 1], Bfr[cur ^ 1]);
            } else if (it + 1 < NK) {
                if (it + 2 < NK) {
                    issue(it + 2, (it + 2) % NSTAGE);
                    CP_COMMIT();
                    CP_WAIT1();
                } else {
                    CP_WAIT0();
                }
                __syncthreads();
                const int nbuf = (it + 1) % NSTAGE;
                ldfrag(su + (uint32_t)nbuf * STAGE_BYTES + OFF_A,
                       su + (uint32_t)nbuf * STAGE_BYTES + OFF_B,
                       0, Afr[cur ^ 1], Bfr[cur ^ 1]);
            }
#pragma unroll
            for (int mf = 0; mf < 4; ++mf)
#pragma unroll
                for (int nf = 0; nf < 4; ++nf)
                    mma16816(acc[mf][nf], Afr[cur] + mf * 4, Bfr[cur] + nf * 2);
        }
    }

    // ---- epilogue ----
#pragma unroll
    for (int mf = 0; mf < 4; ++mf) {
        const int mrow = m0 + wm + mf * 16 + lr;
#pragma unroll
        for (int hh = 0; hh < 2; ++hh) {
            const int m = mrow + hh * 8;
            if (m < cnt) {
                if (PHASE1) {
                    const size_t hb = (size_t)(base + m) * DFF;
#pragma unroll
                    for (int nf = 0; nf < 4; ++nf) {
                        const int c = n0 + wn + nf * 8 + (lid & 3) * 2;
                        const float2 bv = *(const float2*)(bias + (size_t)e * NT + c);
                        float v0 = acc[mf][nf][hh * 2 + 0] + bv.x;
                        float v1 = acc[mf][nf][hh * 2 + 1] + bv.y;
                        v0 = 0.5f * v0 * (1.0f + erff(v0 * 0.7071067811865475f));
                        v1 = 0.5f * v1 * (1.0f + erff(v1 * 0.7071067811865475f));
                        *(uint32_t*)(d_Hf + hb + c) = pack_h2(v0, v1);
                    }
                } else {
                    const int   tok = d_tok[base + m];
                    const float g   = d_gate[base + m];
                    float* op = out + (size_t)tok * DMODEL;
#pragma unroll
                    for (int nf = 0; nf < 4; ++nf) {
                        const int c = n0 + wn + nf * 8 + (lid & 3) * 2;
                        const float2 bv = *(const float2*)(bias + (size_t)e * NT + c);
                        atomicAdd(op + c,     g * (acc[mf][nf][hh * 2 + 0] + bv.x));
                        atomicAdd(op + c + 1, g * (acc[mf][nf][hh * 2 + 1] + bv.y));
                    }
                }
            }
        }
    }
}

// ---------------- launch ----------------
extern "C" void kernel_launch(void* const* d_in, const int* in_sizes, int n_in,
                              void* d_out, int out_size)
{
    const float* x  = (const float*)d_in[0];
    const float* rw = (const float*)d_in[1];
    const float* rb = (const float*)d_in[2];
    const float* w1 = (const float*)d_in[3];
    const float* b1 = (const float*)d_in[4];
    const float* w2 = (const float*)d_in[5];
    const float* b2 = (const float*)d_in[6];
    float* out = (float*)d_out;

    static cudaStream_t s2 = nullptr, s3 = nullptr;
    static cudaEvent_t evF = nullptr, evJ = nullptr, evR = nullptr;
    if (!s2) {
        cudaStreamCreateWithFlags(&s2, cudaStreamNonBlocking);
        cudaStreamCreateWithFlags(&s3, cudaStreamNonBlocking);
        cudaEventCreateWithFlags(&evF, cudaEventDisableTiming);
        cudaEventCreateWithFlags(&evJ, cudaEventDisableTiming);
        cudaEventCreateWithFlags(&evR, cudaEventDisableTiming);
        cudaFuncSetAttribute(gemm_mma<DMODEL, true>,  cudaFuncAttributeMaxDynamicSharedMemorySize, SMEM_BYTES);
        cudaFuncSetAttribute(gemm_mma<DFF,    false>, cudaFuncAttributeMaxDynamicSharedMemorySize, SMEM_BYTES);
    }

    // fork
    cudaEventRecord(evF, 0);
    cudaStreamWaitEvent(s2, evF, 0);
    cudaStreamWaitEvent(s3, evF, 0);

    // s2: w2 conversion + output zeroing (before GEMM2 via evJ)
    wcvt2_kernel<<<1480, 256, 0, s2>>>(w2, out);
    cudaEventRecord(evJ, s2);

    // s3: routing chain
    zero_counts_kernel<<<1, 32, 0, s3>>>();
    router_kernel<<<T_TOK / 4, 128, 0, s3>>>(x, rw, rb);
    prefix_scatter_kernel<<<1, 1024, 0, s3>>>();
    cudaEventRecord(evR, s3);

    // default stream: w1 conversion, then GEMMs
    wcvt1_kernel<<<1184, 256>>>(w1);
    cudaStreamWaitEvent(0, evR, 0);
    gemm_mma<DMODEL, true><<<dim3(DFF / BN, MAXMT), 256, SMEM_BYTES>>>(b1, nullptr);
    cudaStreamWaitEvent(0, evJ, 0);
    gemm_mma<DFF, false><<<dim3(DMODEL / BN, MAXMT), 256, SMEM_BYTES>>>(b2, out);
}

// round 16
// speedup vs baseline: 1.0097x; 1.0097x over previous
#include <cuda_runtime.h>
#include <cuda_fp16.h>
#include <math.h>
#include <stdint.h>

#define T_TOK  4096
#define DMODEL 512
#define DFF    2048
#define NEXP   16
#define TOPK   2
#define NSLOTS (T_TOK*TOPK)

#define BM 128
#define BN 128
#define KC 64            // K elems per stage (64 fp16 = 128B rows)
#define MAXMT (NSLOTS/BM + NEXP)   // 80

// smem: 3 stages x (A 16KB + B 16KB) = 96KB
#define OFF_A       0
#define OFF_B       16384
#define STAGE_BYTES 32768
#define NSTAGE      3
#define SMEM_BYTES  (NSTAGE*STAGE_BYTES)

// ---------------- scratch ----------------
__device__ __half d_xf[(size_t)T_TOK * DMODEL];
__device__ __half d_w1f[(size_t)NEXP * DFF * DMODEL];
__device__ __half d_w2f[(size_t)NEXP * DMODEL * DFF];
__device__ __half d_Hf[(size_t)NSLOTS * DFF];
__device__ int   d_tok[NSLOTS];
__device__ float d_gate[NSLOTS];
__device__ int   d_counts[NEXP];   // histogram (zeroed by prefix_scatter each call)
__device__ int   d_cnte[NEXP];     // snapshot for GEMMs
__device__ int   d_off[NEXP];
__device__ int   d_topk_idx[NSLOTS];
__device__ float d_topk_gate[NSLOTS];
__device__ uint32_t d_mtile[MAXMT];   // (e<<16)|m0
__device__ int   d_nmt;

// ---------------- PTX helpers ----------------
__device__ __forceinline__ uint32_t smem_u32(const void* p) {
    uint32_t a;
    asm("{ .reg .u64 t; cvta.to.shared.u64 t, %1; cvt.u32.u64 %0, t; }" : "=r"(a) : "l"(p));
    return a;
}
__device__ __forceinline__ void cpa16(uint32_t dst, const void* src, uint32_t srcsz) {
    asm volatile("cp.async.cg.shared.global [%0], [%1], 16, %2;"
                 :: "r"(dst), "l"(src), "r"(srcsz) : "memory");
}
#define CP_COMMIT() asm volatile("cp.async.commit_group;" ::: "memory")
#define CP_WAIT1()  asm volatile("cp.async.wait_group 1;" ::: "memory")
#define CP_WAIT0()  asm volatile("cp.async.wait_group 0;" ::: "memory")

__device__ __forceinline__ void mma16816(float* d, const uint32_t* a, const uint32_t* b) {
    asm volatile("mma.sync.aligned.m16n8k16.row.col.f32.f16.f16.f32 "
        "{%0,%1,%2,%3}, {%4,%5,%6,%7}, {%8,%9}, {%0,%1,%2,%3};"
        : "+f"(d[0]), "+f"(d[1]), "+f"(d[2]), "+f"(d[3])
        : "r"(a[0]), "r"(a[1]), "r"(a[2]), "r"(a[3]), "r"(b[0]), "r"(b[1]));
}
__device__ __forceinline__ void ldsm4(uint32_t* r, uint32_t addr) {
    asm volatile("ldmatrix.sync.aligned.m8n8.x4.shared.b16 {%0,%1,%2,%3}, [%4];"
        : "=r"(r[0]), "=r"(r[1]), "=r"(r[2]), "=r"(r[3]) : "r"(addr));
}
__device__ __forceinline__ uint32_t pack_h2(float a, float b) {
    uint32_t r;
    asm("{ .reg .f16 lo, hi; cvt.rn.f16.f32 lo, %1; cvt.rn.f16.f32 hi, %2; mov.b32 %0, {lo, hi}; }"
        : "=r"(r) : "f"(a), "f"(b));
    return r;
}

// SW128 swizzle for 128B-pitch rows
__device__ __forceinline__ uint32_t swz(int row, int cb) {
    return (uint32_t)(row * 128 + (cb ^ ((row & 7) << 4)));
}

// ---------------- router (+ fused x conversion + global histogram) ----------------
__global__ void router_kernel(const float* __restrict__ x,
                              const float* __restrict__ rw,
                              const float* __restrict__ rb)
{
    int warp = (blockIdx.x * blockDim.x + threadIdx.x) >> 5;
    int lane = threadIdx.x & 31;
    if (warp >= T_TOK) return;

    const float* xr = x + (size_t)warp * DMODEL;
    float xv[16];
#pragma unroll
    for (int i = 0; i < 16; i++) xv[i] = xr[lane + 32 * i];

#pragma unroll
    for (int i = 0; i < 16; i++)
        d_xf[(size_t)warp * DMODEL + lane + 32 * i] = __float2half_rn(xv[i]);

    float lg[NEXP];
#pragma unroll
    for (int e = 0; e < NEXP; e++) {
        const float* wr = rw + e * DMODEL;
        float p = 0.f;
#pragma unroll
        for (int i = 0; i < 16; i++) p = fmaf(xv[i], wr[lane + 32 * i], p);
#pragma unroll
        for (int o = 16; o; o >>= 1) p += __shfl_xor_sync(0xffffffffu, p, o);
        lg[e] = p + rb[e];
    }

    if (lane == 0) {
        float mx = lg[0];
#pragma unroll
        for (int e = 1; e < NEXP; e++) mx = fmaxf(mx, lg[e]);
        float pe[NEXP]; float s = 0.f;
#pragma unroll
        for (int e = 0; e < NEXP; e++) { pe[e] = expf(lg[e] - mx); s += pe[e]; }

        int i1 = 0; float v1 = pe[0];
#pragma unroll
        for (int e = 1; e < NEXP; e++) if (pe[e] > v1) { v1 = pe[e]; i1 = e; }
        int i2 = (i1 == 0) ? 1 : 0; float v2 = pe[i2];
#pragma unroll
        for (int e = 0; e < NEXP; e++)
            if (e != i1 && e != ((i1 == 0) ? 1 : 0) && pe[e] > v2) { v2 = pe[e]; i2 = e; }

        float inv = 1.f / s;
        d_topk_idx[2 * warp]      = i1;
        d_topk_gate[2 * warp]     = v1 * inv;
        d_topk_idx[2 * warp + 1]  = i2;
        d_topk_gate[2 * warp + 1] = v2 * inv;
        atomicAdd(&d_counts[i1], 1);
        atomicAdd(&d_counts[i2], 1);
    }
}

// prefix + worklist + scatter (plain smem atomics) + counter self-reset
__global__ void prefix_scatter_kernel() {
    __shared__ int scur[NEXP];
    if (threadIdx.x == 0) {
        int s = 0, nm = 0;
#pragma unroll
        for (int e = 0; e < NEXP; e++) {
            const int c = d_counts[e];
            d_off[e] = s; scur[e] = s; d_cnte[e] = c;
            for (int m0 = 0; m0 < c; m0 += BM)
                d_mtile[nm++] = ((uint32_t)e << 16) | (uint32_t)m0;
            s += c;
        }
        d_nmt = nm;
    }
    __syncthreads();
    for (int i = threadIdx.x; i < NSLOTS; i += blockDim.x) {
        const int e = d_topk_idx[i];
        const int slot = atomicAdd(&scur[e], 1);
        d_tok[slot]  = i >> 1;
        d_gate[slot] = d_topk_gate[i];
    }
    __syncthreads();
    if (threadIdx.x < NEXP) d_counts[threadIdx.x] = 0;   // ready for next replay
}

// w1 fp32 -> fp16
__global__ void wcvt1_kernel(const float* __restrict__ w1) {
    const int n4 = NEXP * DFF * DMODEL / 4;
    uint32_t* o = (uint32_t*)d_w1f;
    for (int i = blockIdx.x * blockDim.x + threadIdx.x; i < n4; i += gridDim.x * blockDim.x) {
        const float4 v = ((const float4*)w1)[i];
        o[2 * i]     = pack_h2(v.x, v.y);
        o[2 * i + 1] = pack_h2(v.z, v.w);
    }
}
// w2 fp32 -> fp16 + zero output buffer
__global__ void wcvt2_kernel(const float* __restrict__ w2, float* __restrict__ out) {
    const int z4 = T_TOK * DMODEL / 4;
    const int n4 = NEXP * DMODEL * DFF / 4;
    uint32_t* o = (uint32_t*)d_w2f;
    for (int i = blockIdx.x * blockDim.x + threadIdx.x; i < n4 + z4; i += gridDim.x * blockDim.x) {
        if (i < z4) {
            ((float4*)out)[i] = make_float4(0.f, 0.f, 0.f, 0.f);
        } else {
            const int j = i - z4;
            const float4 v = ((const float4*)w2)[j];
            o[2 * j]     = pack_h2(v.x, v.y);
            o[2 * j + 1] = pack_h2(v.z, v.w);
        }
    }
}

// ---------------- fp16 HMMA grouped GEMM ----------------
// PHASE1: H = gelu(gather(xf) @ w1^T + b1) -> d_Hf
// PHASE2: out[tok] += gate * (Hf @ w2^T + b2)   (atomic accumulate)
template<int KTOT, bool PHASE1>
__global__ __launch_bounds__(256, 2)
void gemm_mma(const float* __restrict__ bias, float* __restrict__ out)
{
    constexpr int NT = PHASE1 ? DFF : DMODEL;
    constexpr int NK = KTOT / KC;
    if ((int)blockIdx.y >= d_nmt) return;
    const uint32_t mt = d_mtile[blockIdx.y];
    const int e   = (int)(mt >> 16);
    const int m0  = (int)(mt & 0xffffu);
    const int cnt = d_cnte[e];
    const int n0   = blockIdx.x * BN;
    const int base = d_off[e];

    extern __shared__ __align__(128) char smem[];
    const uint32_t su = smem_u32(smem);

    const int tid = threadIdx.x;
    const int wid = tid >> 5;
    const int lid = tid & 31;

    // ---- staging roles ----
    const int r    = tid >> 1;
    const int half = tid & 1;
    const int gm   = m0 + r;
    const __half* arow = d_xf;
    uint32_t aszA = 0;
    if (gm < cnt) {
        int row = PHASE1 ? d_tok[base + gm] : (base + gm);
        arow = (PHASE1 ? d_xf : d_Hf) + (size_t)row * KTOT;
        aszA = 16;
    }
    const __half* brow = (PHASE1 ? d_w1f : d_w2f) + ((size_t)e * NT + n0 + r) * KTOT;

    uint32_t dstc[4];
#pragma unroll
    for (int j = 0; j < 4; j++) dstc[j] = swz(r, half * 64 + j * 16);

    // ---- compute layout ----
    const int wm  = (wid & 1) * 64;
    const int wn  = (wid >> 1) * 32;
    const int lr  = lid >> 2;

    const int mi    = lid >> 3;
    const int rowAl = wm + (mi & 1) * 8 + (lid & 7);
    const int cbA   = (mi >> 1) * 16;
    const int rowBl = wn + (mi >> 1) * 8 + (lid & 7);
    const int cbB   = (mi & 1) * 16;

    float acc[4][4][4];
#pragma unroll
    for (int i = 0; i < 4; i++)
#pragma unroll
        for (int j = 0; j < 4; j++)
#pragma unroll
            for (int q = 0; q < 4; q++) acc[i][j][q] = 0.f;

    auto issue = [&](int it, int buf) {
        const uint32_t sa = su + (uint32_t)buf * STAGE_BYTES + OFF_A;
        const uint32_t sb = su + (uint32_t)buf * STAGE_BYTES + OFF_B;
        const __half* pa = arow + it * KC + half * 32;
        const __half* pb = brow + it * KC + half * 32;
#pragma unroll
        for (int j = 0; j < 4; j++) {
            cpa16(sa + dstc[j], pa + j * 8, aszA);
            cpa16(sb + dstc[j], pb + j * 8, 16);
        }
    };

    uint32_t Afr[2][16], Bfr[2][8];

    auto ldfrag = [&](uint32_t sa, uint32_t sbb, int kb2, uint32_t* A, uint32_t* B) {
#pragma unroll
        for (int mf = 0; mf < 4; ++mf)
            ldsm4(A + mf * 4, sa + swz(rowAl + mf * 16, kb2 + cbA));
#pragma unroll
        for (int p = 0; p < 2; ++p)
            ldsm4(B + p * 4, sbb + swz(rowBl + p * 16, kb2 + cbB));
    };

    issue(0, 0); CP_COMMIT();
    issue(1, 1); CP_COMMIT();
    CP_WAIT1();
    __syncthreads();
    ldfrag(su + OFF_A, su + OFF_B, 0, Afr[0], Bfr[0]);

    for (int it = 0; it < NK; ++it) {
        const int buf = it % NSTAGE;
        const uint32_t sa  = su + (uint32_t)buf * STAGE_BYTES + OFF_A;
        const uint32_t sbb = su + (uint32_t)buf * STAGE_BYTES + OFF_B;
#pragma unroll
        for (int kk = 0; kk < 4; ++kk) {
            const int cur = kk & 1;
            if (kk < 3) {
                ldfrag(sa, sbb, (kk + 1) * 32, Afr[cur ^ 1], Bfr[cur ^ 1]);
            } else if (it + 1 < NK) {
                if (it + 2 < NK) {
                    issue(it + 2, (it + 2) % NSTAGE);
                    CP_COMMIT();
                    CP_WAIT1();
                } else {
                    CP_WAIT0();
                }
                __syncthreads();
                const int nbuf = (it + 1) % NSTAGE;
                ldfrag(su + (uint32_t)nbuf * STAGE_BYTES + OFF_A,
                       su + (uint32_t)nbuf * STAGE_BYTES + OFF_B,
                       0, Afr[cur ^ 1], Bfr[cur ^ 1]);
            }
#pragma unroll
            for (int mf = 0; mf < 4; ++mf)
#pragma unroll
                for (int nf = 0; nf < 4; ++nf)
                    mma16816(acc[mf][nf], Afr[cur] + mf * 4, Bfr[cur] + nf * 2);
        }
    }

    // ---- epilogue ----
#pragma unroll
    for (int mf = 0; mf < 4; ++mf) {
        const int mrow = m0 + wm + mf * 16 + lr;
#pragma unroll
        for (int hh = 0; hh < 2; ++hh) {
            const int m = mrow + hh * 8;
            if (m < cnt) {
                if (PHASE1) {
                    const size_t hb = (size_t)(base + m) * DFF;
#pragma unroll
                    for (int nf = 0; nf < 4; ++nf) {
                        const int c = n0 + wn + nf * 8 + (lid & 3) * 2;
                        const float2 bv = *(const float2*)(bias + (size_t)e * NT + c);
                        float v0 = acc[mf][nf][hh * 2 + 0] + bv.x;
                        float v1 = acc[mf][nf][hh * 2 + 1] + bv.y;
                        v0 = 0.5f * v0 * (1.0f + erff(v0 * 0.7071067811865475f));
                        v1 = 0.5f * v1 * (1.0f + erff(v1 * 0.7071067811865475f));
                        *(uint32_t*)(d_Hf + hb + c) = pack_h2(v0, v1);
                    }
                } else {
                    const int   tok = d_tok[base + m];
                    const float g   = d_gate[base + m];
                    float* op = out + (size_t)tok * DMODEL;
#pragma unroll
                    for (int nf = 0; nf < 4; ++nf) {
                        const int c = n0 + wn + nf * 8 + (lid & 3) * 2;
                        const float2 bv = *(const float2*)(bias + (size_t)e * NT + c);
                        atomicAdd(op + c,     g * (acc[mf][nf][hh * 2 + 0] + bv.x));
                        atomicAdd(op + c + 1, g * (acc[mf][nf][hh * 2 + 1] + bv.y));
                    }
                }
            }
        }
    }
}

// ---------------- launch ----------------
extern "C" void kernel_launch(void* const* d_in, const int* in_sizes, int n_in,
                              void* d_out, int out_size)
{
    const float* x  = (const float*)d_in[0];
    const float* rw = (const float*)d_in[1];
    const float* rb = (const float*)d_in[2];
    const float* w1 = (const float*)d_in[3];
    const float* b1 = (const float*)d_in[4];
    const float* w2 = (const float*)d_in[5];
    const float* b2 = (const float*)d_in[6];
    float* out = (float*)d_out;

    static cudaStream_t s2 = nullptr, s3 = nullptr;
    static cudaEvent_t evF = nullptr, evJ = nullptr, evR = nullptr;
    if (!s2) {
        cudaStreamCreateWithFlags(&s2, cudaStreamNonBlocking);
        cudaStreamCreateWithFlags(&s3, cudaStreamNonBlocking);
        cudaEventCreateWithFlags(&evF, cudaEventDisableTiming);
        cudaEventCreateWithFlags(&evJ, cudaEventDisableTiming);
        cudaEventCreateWithFlags(&evR, cudaEventDisableTiming);
        cudaFuncSetAttribute(gemm_mma<DMODEL, true>,  cudaFuncAttributeMaxDynamicSharedMemorySize, SMEM_BYTES);
        cudaFuncSetAttribute(gemm_mma<DFF,    false>, cudaFuncAttributeMaxDynamicSharedMemorySize, SMEM_BYTES);
    }

    // fork
    cudaEventRecord(evF, 0);
    cudaStreamWaitEvent(s2, evF, 0);
    cudaStreamWaitEvent(s3, evF, 0);

    // s2: w2 conversion + output zeroing (before GEMM2 via evJ)
    wcvt2_kernel<<<1480, 256, 0, s2>>>(w2, out);
    cudaEventRecord(evJ, s2);

    // s3: routing chain (counts already zero: module-init on call 1, self-reset after)
    router_kernel<<<T_TOK / 4, 128, 0, s3>>>(x, rw, rb);
    prefix_scatter_kernel<<<1, 1024, 0, s3>>>();
    cudaEventRecord(evR, s3);

    // default stream: w1 conversion, then GEMMs
    wcvt1_kernel<<<1184, 256>>>(w1);
    cudaStreamWaitEvent(0, evR, 0);
    gemm_mma<DMODEL, true><<<dim3(DFF / BN, MAXMT), 256, SMEM_BYTES>>>(b1, nullptr);
    cudaStreamWaitEvent(0, evJ, 0);
    gemm_mma<DFF, false><<<dim3(DMODEL / BN, MAXMT), 256, SMEM_BYTES>>>(b2, out);
}

// round 17
// speedup vs baseline: 1.0401x; 1.0301x over previous
#include <cuda_runtime.h>
#include <cuda_fp16.h>
#include <math.h>
#include <stdint.h>

#define T_TOK  4096
#define DMODEL 512
#define DFF    2048
#define NEXP   16
#define TOPK   2
#define NSLOTS (T_TOK*TOPK)
#define ECAP   4096              // fixed per-expert slot capacity
#define ESLOTS (NEXP*ECAP)

#define BM 128
#define BN 128
#define KC 64            // K elems per stage (64 fp16 = 128B rows)
#define MAXMT (NSLOTS/BM + NEXP)   // 80

// smem: 3 stages x (A 16KB + B 16KB) = 96KB
#define OFF_A       0
#define OFF_B       16384
#define STAGE_BYTES 32768
#define NSTAGE      3
#define SMEM_BYTES  (NSTAGE*STAGE_BYTES)

// ---------------- scratch ----------------
__device__ __half d_xf[(size_t)T_TOK * DMODEL];
__device__ __half d_w1f[(size_t)NEXP * DFF * DMODEL];
__device__ __half d_w2f[(size_t)NEXP * DMODEL * DFF];
__device__ __half d_Hf[(size_t)ESLOTS * DFF];       // 256MB, fixed-capacity regions
__device__ int   d_tok[ESLOTS];
__device__ float d_gate[ESLOTS];
__device__ int   d_counts[NEXP];
__device__ int   d_topk_idx[NSLOTS];
__device__ float d_topk_gate[NSLOTS];
__device__ uint32_t d_mtile[MAXMT];   // (e<<16)|m0
__device__ int   d_nmt;

// ---------------- PTX helpers ----------------
__device__ __forceinline__ uint32_t smem_u32(const void* p) {
    uint32_t a;
    asm("{ .reg .u64 t; cvta.to.shared.u64 t, %1; cvt.u32.u64 %0, t; }" : "=r"(a) : "l"(p));
    return a;
}
__device__ __forceinline__ void cpa16(uint32_t dst, const void* src, uint32_t srcsz) {
    asm volatile("cp.async.cg.shared.global [%0], [%1], 16, %2;"
                 :: "r"(dst), "l"(src), "r"(srcsz) : "memory");
}
#define CP_COMMIT() asm volatile("cp.async.commit_group;" ::: "memory")
#define CP_WAIT1()  asm volatile("cp.async.wait_group 1;" ::: "memory")
#define CP_WAIT0()  asm volatile("cp.async.wait_group 0;" ::: "memory")

__device__ __forceinline__ void mma16816(float* d, const uint32_t* a, const uint32_t* b) {
    asm volatile("mma.sync.aligned.m16n8k16.row.col.f32.f16.f16.f32 "
        "{%0,%1,%2,%3}, {%4,%5,%6,%7}, {%8,%9}, {%0,%1,%2,%3};"
        : "+f"(d[0]), "+f"(d[1]), "+f"(d[2]), "+f"(d[3])
        : "r"(a[0]), "r"(a[1]), "r"(a[2]), "r"(a[3]), "r"(b[0]), "r"(b[1]));
}
__device__ __forceinline__ void ldsm4(uint32_t* r, uint32_t addr) {
    asm volatile("ldmatrix.sync.aligned.m8n8.x4.shared.b16 {%0,%1,%2,%3}, [%4];"
        : "=r"(r[0]), "=r"(r[1]), "=r"(r[2]), "=r"(r[3]) : "r"(addr));
}
__device__ __forceinline__ uint32_t pack_h2(float a, float b) {
    uint32_t r;
    asm("{ .reg .f16 lo, hi; cvt.rn.f16.f32 lo, %1; cvt.rn.f16.f32 hi, %2; mov.b32 %0, {lo, hi}; }"
        : "=r"(r) : "f"(a), "f"(b));
    return r;
}

// SW128 swizzle for 128B-pitch rows
__device__ __forceinline__ uint32_t swz(int row, int cb) {
    return (uint32_t)(row * 128 + (cb ^ ((row & 7) << 4)));
}

// ---------------- router (+ fused x fp32->fp16 conversion; NO atomics) ----------------
__global__ void router_kernel(const float* __restrict__ x,
                              const float* __restrict__ rw,
                              const float* __restrict__ rb)
{
    int warp = (blockIdx.x * blockDim.x + threadIdx.x) >> 5;
    int lane = threadIdx.x & 31;
    if (warp >= T_TOK) return;

    const float* xr = x + (size_t)warp * DMODEL;
    float xv[16];
#pragma unroll
    for (int i = 0; i < 16; i++) xv[i] = xr[lane + 32 * i];

#pragma unroll
    for (int i = 0; i < 16; i++)
        d_xf[(size_t)warp * DMODEL + lane + 32 * i] = __float2half_rn(xv[i]);

    float lg[NEXP];
#pragma unroll
    for (int e = 0; e < NEXP; e++) {
        const float* wr = rw + e * DMODEL;
        float p = 0.f;
#pragma unroll
        for (int i = 0; i < 16; i++) p = fmaf(xv[i], wr[lane + 32 * i], p);
#pragma unroll
        for (int o = 16; o; o >>= 1) p += __shfl_xor_sync(0xffffffffu, p, o);
        lg[e] = p + rb[e];
    }

    if (lane == 0) {
        float mx = lg[0];
#pragma unroll
        for (int e = 1; e < NEXP; e++) mx = fmaxf(mx, lg[e]);
        float pe[NEXP]; float s = 0.f;
#pragma unroll
        for (int e = 0; e < NEXP; e++) { pe[e] = expf(lg[e] - mx); s += pe[e]; }

        int i1 = 0; float v1 = pe[0];
#pragma unroll
        for (int e = 1; e < NEXP; e++) if (pe[e] > v1) { v1 = pe[e]; i1 = e; }
        int i2 = (i1 == 0) ? 1 : 0; float v2 = pe[i2];
#pragma unroll
        for (int e = 0; e < NEXP; e++)
            if (e != i1 && e != ((i1 == 0) ? 1 : 0) && pe[e] > v2) { v2 = pe[e]; i2 = e; }

        float inv = 1.f / s;
        d_topk_idx[2 * warp]      = i1;
        d_topk_gate[2 * warp]     = v1 * inv;
        d_topk_idx[2 * warp + 1]  = i2;
        d_topk_gate[2 * warp + 1] = v2 * inv;
    }
}

// single-pass scatter into fixed-capacity regions + worklist build
__global__ void scatter_kernel() {
    __shared__ int scur[NEXP];
    if (threadIdx.x < NEXP) scur[threadIdx.x] = 0;
    __syncthreads();
    for (int i = threadIdx.x; i < NSLOTS; i += blockDim.x) {
        const int e = d_topk_idx[i];
        const int slot = atomicAdd(&scur[e], 1);
        d_tok[(e << 12) + slot]  = i >> 1;
        d_gate[(e << 12) + slot] = d_topk_gate[i];
    }
    __syncthreads();
    if (threadIdx.x == 0) {
        int nm = 0;
#pragma unroll
        for (int e = 0; e < NEXP; e++) {
            const int c = scur[e];
            d_counts[e] = c;
            for (int m0 = 0; m0 < c; m0 += BM)
                d_mtile[nm++] = ((uint32_t)e << 16) | (uint32_t)m0;
        }
        d_nmt = nm;
    }
}

// w1 fp32 -> fp16
__global__ void wcvt1_kernel(const float* __restrict__ w1) {
    const int n4 = NEXP * DFF * DMODEL / 4;
    uint32_t* o = (uint32_t*)d_w1f;
    for (int i = blockIdx.x * blockDim.x + threadIdx.x; i < n4; i += gridDim.x * blockDim.x) {
        const float4 v = ((const float4*)w1)[i];
        o[2 * i]     = pack_h2(v.x, v.y);
        o[2 * i + 1] = pack_h2(v.z, v.w);
    }
}
// w2 fp32 -> fp16
__global__ void wcvt2_kernel(const float* __restrict__ w2) {
    const int n4 = NEXP * DMODEL * DFF / 4;
    uint32_t* o = (uint32_t*)d_w2f;
    for (int i = blockIdx.x * blockDim.x + threadIdx.x; i < n4; i += gridDim.x * blockDim.x) {
        const float4 v = ((const float4*)w2)[i];
        o[2 * i]     = pack_h2(v.x, v.y);
        o[2 * i + 1] = pack_h2(v.z, v.w);
    }
}
// zero the output buffer (GEMM2 accumulates into it atomically)
__global__ void zero_out_kernel(float* __restrict__ out) {
    const int n4 = T_TOK * DMODEL / 4;
    for (int i = blockIdx.x * blockDim.x + threadIdx.x; i < n4; i += gridDim.x * blockDim.x)
        ((float4*)out)[i] = make_float4(0.f, 0.f, 0.f, 0.f);
}

// ---------------- fp16 HMMA grouped GEMM ----------------
// PHASE1: H = gelu(gather(xf) @ w1^T + b1) -> d_Hf  (region base e<<12)
// PHASE2: out[tok] += gate * (Hf @ w2^T + b2)        (atomic accumulate)
template<int KTOT, bool PHASE1>
__global__ __launch_bounds__(256, 2)
void gemm_mma(const float* __restrict__ bias, float* __restrict__ out)
{
    constexpr int NT = PHASE1 ? DFF : DMODEL;
    constexpr int NK = KTOT / KC;
    if ((int)blockIdx.y >= d_nmt) return;
    const uint32_t mt = d_mtile[blockIdx.y];
    const int e   = (int)(mt >> 16);
    const int m0  = (int)(mt & 0xffffu);
    const int cnt = d_counts[e];
    const int n0   = blockIdx.x * BN;
    const int base = e << 12;

    extern __shared__ __align__(128) char smem[];
    const uint32_t su = smem_u32(smem);

    const int tid = threadIdx.x;
    const int wid = tid >> 5;
    const int lid = tid & 31;

    // ---- staging roles ----
    const int r    = tid >> 1;
    const int half = tid & 1;
    const int gm   = m0 + r;
    const __half* arow = d_xf;
    uint32_t aszA = 0;
    if (gm < cnt) {
        int row = PHASE1 ? d_tok[base + gm] : (base + gm);
        arow = (PHASE1 ? d_xf : d_Hf) + (size_t)row * KTOT;
        aszA = 16;
    }
    const __half* brow = (PHASE1 ? d_w1f : d_w2f) + ((size_t)e * NT + n0 + r) * KTOT;

    uint32_t dstc[4];
#pragma unroll
    for (int j = 0; j < 4; j++) dstc[j] = swz(r, half * 64 + j * 16);

    // ---- compute layout ----
    const int wm  = (wid & 1) * 64;
    const int wn  = (wid >> 1) * 32;
    const int lr  = lid >> 2;

    const int mi    = lid >> 3;
    const int rowAl = wm + (mi & 1) * 8 + (lid & 7);
    const int cbA   = (mi >> 1) * 16;
    const int rowBl = wn + (mi >> 1) * 8 + (lid & 7);
    const int cbB   = (mi & 1) * 16;

    float acc[4][4][4];
#pragma unroll
    for (int i = 0; i < 4; i++)
#pragma unroll
        for (int j = 0; j < 4; j++)
#pragma unroll
            for (int q = 0; q < 4; q++) acc[i][j][q] = 0.f;

    auto issue = [&](int it, int buf) {
        const uint32_t sa = su + (uint32_t)buf * STAGE_BYTES + OFF_A;
        const uint32_t sb = su + (uint32_t)buf * STAGE_BYTES + OFF_B;
        const __half* pa = arow + it * KC + half * 32;
        const __half* pb = brow + it * KC + half * 32;
#pragma unroll
        for (int j = 0; j < 4; j++) {
            cpa16(sa + dstc[j], pa + j * 8, aszA);
            cpa16(sb + dstc[j], pb + j * 8, 16);
        }
    };

    uint32_t Afr[2][16], Bfr[2][8];

    auto ldfrag = [&](uint32_t sa, uint32_t sbb, int kb2, uint32_t* A, uint32_t* B) {
#pragma unroll
        for (int mf = 0; mf < 4; ++mf)
            ldsm4(A + mf * 4, sa + swz(rowAl + mf * 16, kb2 + cbA));
#pragma unroll
        for (int p = 0; p < 2; ++p)
            ldsm4(B + p * 4, sbb + swz(rowBl + p * 16, kb2 + cbB));
    };

    issue(0, 0); CP_COMMIT();
    issue(1, 1); CP_COMMIT();
    CP_WAIT1();
    __syncthreads();
    ldfrag(su + OFF_A, su + OFF_B, 0, Afr[0], Bfr[0]);

    for (int it = 0; it < NK; ++it) {
        const int buf = it % NSTAGE;
        const uint32_t sa  = su + (uint32_t)buf * STAGE_BYTES + OFF_A;
        const uint32_t sbb = su + (uint32_t)buf * STAGE_BYTES + OFF_B;
#pragma unroll
        for (int kk = 0; kk < 4; ++kk) {
            const int cur = kk & 1;
            if (kk < 3) {
                ldfrag(sa, sbb, (kk + 1) * 32, Afr[cur ^ 1], Bfr[cur ^ 1]);
            } else if (it + 1 < NK) {
                if (it + 2 < NK) {
                    issue(it + 2, (it + 2) % NSTAGE);
                    CP_COMMIT();
                    CP_WAIT1();
                } else {
                    CP_WAIT0();
                }
                __syncthreads();
                const int nbuf = (it + 1) % NSTAGE;
                ldfrag(su + (uint32_t)nbuf * STAGE_BYTES + OFF_A,
                       su + (uint32_t)nbuf * STAGE_BYTES + OFF_B,
                       0, Afr[cur ^ 1], Bfr[cur ^ 1]);
            }
#pragma unroll
            for (int mf = 0; mf < 4; ++mf)
#pragma unroll
                for (int nf = 0; nf < 4; ++nf)
                    mma16816(acc[mf][nf], Afr[cur] + mf * 4, Bfr[cur] + nf * 2);
        }
    }

    // ---- epilogue ----
#pragma unroll
    for (int mf = 0; mf < 4; ++mf) {
        const int mrow = m0 + wm + mf * 16 + lr;
#pragma unroll
        for (int hh = 0; hh < 2; ++hh) {
            const int m = mrow + hh * 8;
            if (m < cnt) {
                if (PHASE1) {
                    const size_t hb = (size_t)(base + m) * DFF;
#pragma unroll
                    for (int nf = 0; nf < 4; ++nf) {
                        const int c = n0 + wn + nf * 8 + (lid & 3) * 2;
                        const float2 bv = *(const float2*)(bias + (size_t)e * NT + c);
                        float v0 = acc[mf][nf][hh * 2 + 0] + bv.x;
                        float v1 = acc[mf][nf][hh * 2 + 1] + bv.y;
                        v0 = 0.5f * v0 * (1.0f + erff(v0 * 0.7071067811865475f));
                        v1 = 0.5f * v1 * (1.0f + erff(v1 * 0.7071067811865475f));
                        *(uint32_t*)(d_Hf + hb + c) = pack_h2(v0, v1);
                    }
                } else {
                    const int   tok = d_tok[base + m];
                    const float g   = d_gate[base + m];
                    float* op = out + (size_t)tok * DMODEL;
#pragma unroll
                    for (int nf = 0; nf < 4; ++nf) {
                        const int c = n0 + wn + nf * 8 + (lid & 3) * 2;
                        const float2 bv = *(const float2*)(bias + (size_t)e * NT + c);
                        atomicAdd(op + c,     g * (acc[mf][nf][hh * 2 + 0] + bv.x));
                        atomicAdd(op + c + 1, g * (acc[mf][nf][hh * 2 + 1] + bv.y));
                    }
                }
            }
        }
    }
}

// ---------------- launch ----------------
extern "C" void kernel_launch(void* const* d_in, const int* in_sizes, int n_in,
                              void* d_out, int out_size)
{
    const float* x  = (const float*)d_in[0];
    const float* rw = (const float*)d_in[1];
    const float* rb = (const float*)d_in[2];
    const float* w1 = (const float*)d_in[3];
    const float* b1 = (const float*)d_in[4];
    const float* w2 = (const float*)d_in[5];
    const float* b2 = (const float*)d_in[6];
    float* out = (float*)d_out;

    static cudaStream_t s2 = nullptr, s3 = nullptr;
    static cudaEvent_t evF = nullptr, evJ = nullptr, evR = nullptr;
    if (!s2) {
        cudaStreamCreateWithFlags(&s2, cudaStreamNonBlocking);
        cudaStreamCreateWithFlags(&s3, cudaStreamNonBlocking);
        cudaEventCreateWithFlags(&evF, cudaEventDisableTiming);
        cudaEventCreateWithFlags(&evJ, cudaEventDisableTiming);
        cudaEventCreateWithFlags(&evR, cudaEventDisableTiming);
        cudaFuncSetAttribute(gemm_mma<DMODEL, true>,  cudaFuncAttributeMaxDynamicSharedMemorySize, SMEM_BYTES);
        cudaFuncSetAttribute(gemm_mma<DFF,    false>, cudaFuncAttributeMaxDynamicSharedMemorySize, SMEM_BYTES);
    }

    // fork
    cudaEventRecord(evF, 0);
    cudaStreamWaitEvent(s2, evF, 0);
    cudaStreamWaitEvent(s3, evF, 0);

    // s2: zero output + w2 conversion (all before GEMM2 via evJ)
    zero_out_kernel<<<296, 256, 0, s2>>>(out);
    wcvt2_kernel<<<1184, 256, 0, s2>>>(w2);
    cudaEventRecord(evJ, s2);

    // s3: routing chain (single-pass scatter, no prefix)
    router_kernel<<<T_TOK / 4, 128, 0, s3>>>(x, rw, rb);
    scatter_kernel<<<1, 1024, 0, s3>>>();
    cudaEventRecord(evR, s3);

    // default stream: w1 conversion, then GEMMs
    wcvt1_kernel<<<1184, 256>>>(w1);
    cudaStreamWaitEvent(0, evR, 0);
    gemm_mma<DMODEL, true><<<dim3(DFF / BN, MAXMT), 256, SMEM_BYTES>>>(b1, nullptr);
    cudaStreamWaitEvent(0, evJ, 0);
    gemm_mma<DFF, false><<<dim3(DMODEL / BN, MAXMT), 256, SMEM_BYTES>>>(b2, out);
}